// round 14
// baseline (speedup 1.0000x reference)
#include <cuda_runtime.h>
#include <cuda_fp16.h>
#include <cstdint>

#define N_NODES 200000
#define N_EDGES 6400000
#define HIDDEN  200
#define NHID    6
#define TM      128
#define THREADS 256
#define NCTA    ((N_NODES + TM - 1) / TM)   // 1563

#define NKC     13                  // k16 chunks (K=200 padded to 208)
#define ASTRIDE 432                 // bytes per activation row (216 fp16, conflict-free)

// smem offsets (bytes) — total 62432, 1 CTA/SM (regs are the limiter)
#define A_OFF    0                  // 128 x 432 = 55296
#define BIAS_OFF 55296              // 6*200 f32 = 4800
#define WOUT_OFF 60096              // 200 f32 = 800
#define H0_OFF   60896              // 128 f32 = 512
#define ZP_OFF   61408              // 2*128 f32 = 1024
#define SMEM_BYTES 62432

__device__ float g_agg[N_NODES];
// per-lane packed B fragments: idx = ((l*13+kc)*25+nt)*32 + lane -> uint2 {b0,b1}
__device__ __align__(16) uint2 g_wimg[NHID * NKC * 25 * 32];   // 499200 B (L2-resident)

// ---------------- tiny kernels ----------------
__global__ void k_zero() {
    int i = blockIdx.x * blockDim.x + threadIdx.x;
    if (i < N_NODES) g_agg[i] = 0.0f;
}

__global__ void k_scatter(const float* __restrict__ x, const int* __restrict__ ei) {
    int i = blockIdx.x * blockDim.x + threadIdx.x;
    if (i < N_EDGES / 4) {
        const int4 s = reinterpret_cast<const int4*>(ei)[i];
        const int4 d = reinterpret_cast<const int4*>(ei + N_EDGES)[i];
        atomicAdd(&g_agg[d.x], x[s.x]);
        atomicAdd(&g_agg[d.y], x[s.y]);
        atomicAdd(&g_agg[d.z], x[s.z]);
        atomicAdd(&g_agg[d.w], x[s.w]);
    }
}

__device__ __forceinline__ uint32_t packh2(float v0, float v1) {
    __half2 h = __floats2half2_rn(v0, v1);
    return *reinterpret_cast<uint32_t*>(&h);
}

__global__ void k_prep(const float* __restrict__ w_hid) {
    int idx = blockIdx.x * blockDim.x + threadIdx.x;
    if (idx >= NHID * NKC * 25 * 32) return;
    int lane = idx & 31;
    int u = idx >> 5;
    int nt = u % 25; u /= 25;
    int kc = u % NKC; int l = u / NKC;
    int t = lane & 3, g = lane >> 2;
    int n = nt * 8 + g;
    int k0 = kc * 16 + t * 2;
    float w00 = (k0     < HIDDEN) ? w_hid[((size_t)l * HIDDEN + k0    ) * HIDDEN + n] : 0.f;
    float w01 = (k0 + 1 < HIDDEN) ? w_hid[((size_t)l * HIDDEN + k0 + 1) * HIDDEN + n] : 0.f;
    float w10 = (k0 + 8 < HIDDEN) ? w_hid[((size_t)l * HIDDEN + k0 + 8) * HIDDEN + n] : 0.f;
    float w11 = (k0 + 9 < HIDDEN) ? w_hid[((size_t)l * HIDDEN + k0 + 9) * HIDDEN + n] : 0.f;
    uint2 v;
    v.x = packh2(w00, w01);
    v.y = packh2(w10, w11);
    g_wimg[idx] = v;
}

// ---------------- asm helpers ----------------
__device__ __forceinline__ uint32_t s2u(const void* p) {
    uint32_t a;
    asm("{ .reg .u64 t; cvta.to.shared.u64 t, %1; cvt.u32.u64 %0, t; }" : "=r"(a) : "l"(p));
    return a;
}
__device__ __forceinline__ void ldsm4(uint32_t* r, uint32_t a) {
    asm volatile("ldmatrix.sync.aligned.m8n8.x4.shared.b16 {%0,%1,%2,%3}, [%4];"
        : "=r"(r[0]), "=r"(r[1]), "=r"(r[2]), "=r"(r[3]) : "r"(a));
}
__device__ __forceinline__ void sts32(uint32_t a, uint32_t v) {
    asm volatile("st.shared.u32 [%0], %1;" :: "r"(a), "r"(v));
}
__device__ __forceinline__ void mma16816(float* d, const uint32_t* a, uint32_t b0, uint32_t b1) {
    asm volatile("mma.sync.aligned.m16n8k16.row.col.f32.f16.f16.f32 "
        "{%0,%1,%2,%3}, {%4,%5,%6,%7}, {%8,%9}, {%0,%1,%2,%3};"
        : "+f"(d[0]), "+f"(d[1]), "+f"(d[2]), "+f"(d[3])
        : "r"(a[0]), "r"(a[1]), "r"(a[2]), "r"(a[3]), "r"(b0), "r"(b1));
}

// ---------------- layer MMA loop: warp = M32 x NNTW n8-tiles, B double-buffered from L2/L1 ----
// d layout: d[mh*NNTW + nt][4], mh in {0,1} = rows +0..15 / +16..31
template<int NNTW>
__device__ __forceinline__ void layer_mmas(
    float (*d)[4], const uint2* __restrict__ gwl, uint32_t aAddr)
{
    uint2    B[2][NNTW];
    uint32_t a[2][8];

    ldsm4(&a[0][0], aAddr);
    ldsm4(&a[0][4], aAddr + 16 * ASTRIDE);
    #pragma unroll
    for (int nt = 0; nt < NNTW; ++nt) B[0][nt] = __ldg(gwl + nt * 32);

    #pragma unroll
    for (int kc = 0; kc < NKC; ++kc) {
        const int cur = kc & 1, nxt = cur ^ 1;
        if (kc + 1 < NKC) {
            ldsm4(&a[nxt][0], aAddr + (kc + 1) * 32);
            ldsm4(&a[nxt][4], aAddr + 16 * ASTRIDE + (kc + 1) * 32);
            const uint2* gk = gwl + (size_t)(kc + 1) * 800;
            #pragma unroll
            for (int nt = 0; nt < NNTW; ++nt) B[nxt][nt] = __ldg(gk + nt * 32);
        }
        #pragma unroll
        for (int nt = 0; nt < NNTW; ++nt) {
            mma16816(d[nt],        &a[cur][0], B[cur][nt].x, B[cur][nt].y);
            mma16816(d[NNTW + nt], &a[cur][4], B[cur][nt].x, B[cur][nt].y);
        }
    }
}

template<int NTB, int NNTW>
__device__ __forceinline__ void epi_store(
    const float (*d)[4], const float* biasL, int mg, int g, int t, uint32_t sb)
{
    #pragma unroll
    for (int mh = 0; mh < 2; ++mh) {
        const uint32_t off0 = (uint32_t)(mg * 32 + mh * 16 + g) * ASTRIDE;
        #pragma unroll
        for (int nt = 0; nt < NNTW; ++nt) {
            const float* dd = d[mh * NNTW + nt];
            int c0 = 8 * (NTB + nt) + 2 * t;
            float b0 = biasL[c0], b1 = biasL[c0 + 1];
            float v0 = fmaxf(dd[0] + b0, 0.f), v1 = fmaxf(dd[1] + b1, 0.f);
            float v2 = fmaxf(dd[2] + b0, 0.f), v3 = fmaxf(dd[3] + b1, 0.f);
            uint32_t a0 = off0 + (uint32_t)c0 * 2;
            sts32(sb + A_OFF + a0, packh2(v0, v1));
            sts32(sb + A_OFF + a0 + 8 * ASTRIDE, packh2(v2, v3));
        }
    }
}

template<int NTB, int NNTW>
__device__ __forceinline__ void epi_final(
    const float (*d)[4], const float* biasL, const float* woutS,
    float* zp, int ng, int mg, int g, int t)
{
    #pragma unroll
    for (int mh = 0; mh < 2; ++mh) {
        float z0 = 0.f, z1 = 0.f;
        #pragma unroll
        for (int nt = 0; nt < NNTW; ++nt) {
            const float* dd = d[mh * NNTW + nt];
            int c0 = 8 * (NTB + nt) + 2 * t;
            float b0 = biasL[c0], b1 = biasL[c0 + 1];
            float w0 = woutS[c0], w1 = woutS[c0 + 1];
            z0 = fmaf(fmaxf(dd[0] + b0, 0.f), w0, z0);
            z0 = fmaf(fmaxf(dd[1] + b1, 0.f), w1, z0);
            z1 = fmaf(fmaxf(dd[2] + b0, 0.f), w0, z1);
            z1 = fmaf(fmaxf(dd[3] + b1, 0.f), w1, z1);
        }
        z0 += __shfl_xor_sync(0xffffffffu, z0, 1);
        z0 += __shfl_xor_sync(0xffffffffu, z0, 2);
        z1 += __shfl_xor_sync(0xffffffffu, z1, 1);
        z1 += __shfl_xor_sync(0xffffffffu, z1, 2);
        if (t == 0) {
            int rl = mg * 32 + mh * 16 + g;
            zp[ng * TM + rl]     = z0;
            zp[ng * TM + rl + 8] = z1;
        }
    }
}

// ---------------- fused GraphConv + MLP + sigmoid ----------------
__global__ void __launch_bounds__(THREADS, 1) k_mlp(
    const float* __restrict__ x,
    const float* __restrict__ w_rel, const float* __restrict__ b_rel,
    const float* __restrict__ w_root,
    const float* __restrict__ w_in,  const float* __restrict__ b_in,
    const float* __restrict__ b_hid,
    const float* __restrict__ w_out, const float* __restrict__ b_out,
    float* __restrict__ out)
{
    extern __shared__ char smem[];
    const uint32_t sb = s2u(smem);
    const int tid  = threadIdx.x;
    const int warp = tid >> 5;
    const int lane = tid & 31;
    const int ng   = warp & 1;         // n-half: tiles 0..12 / 13..24 (SMSP pairs share ng -> L1 B dedup)
    const int mg   = warp >> 1;        // m-group: rows mg*32 .. +31
    const int g    = lane >> 2;
    const int t    = lane & 3;
    const int row0 = blockIdx.x * TM;

    float* biasS = reinterpret_cast<float*>(smem + BIAS_OFF);   // [6][200]
    float* woutS = reinterpret_cast<float*>(smem + WOUT_OFF);
    float* h0S   = reinterpret_cast<float*>(smem + H0_OFF);
    float* zp    = reinterpret_cast<float*>(smem + ZP_OFF);     // [2][128]

    // stage small vectors + h0
    if (tid < HIDDEN) woutS[tid] = __ldg(w_out + tid);
    for (int i = tid; i < NHID * HIDDEN; i += THREADS) biasS[i] = __ldg(b_hid + i);
    if (tid < TM) {
        int r = row0 + tid;
        float a  = (r < N_NODES) ? g_agg[r] : 0.0f;
        float xv = (r < N_NODES) ? __ldg(x + r) : 0.0f;
        h0S[tid] = a * __ldg(w_rel) + __ldg(b_rel) + xv * __ldg(w_root);
    }
    __syncthreads();

    // layer-1 activations (rank-1): A[r][k] = relu(h0[r]*w_in[k]+b_in[k]), k>=200 -> 0
    for (int i = tid; i < TM * 208; i += THREADS) {
        int r = i / 208, k = i - r * 208;
        float v = 0.0f;
        if (k < HIDDEN) v = fmaxf(fmaf(h0S[r], __ldg(w_in + k), __ldg(b_in + k)), 0.0f);
        *reinterpret_cast<__half*>(smem + A_OFF + r * ASTRIDE + k * 2) = __float2half_rn(v);
    }
    __syncthreads();

    // ldmatrix per-lane address (rows mg*32 .. +15; second half at +16*ASTRIDE)
    const int lrow = lane & 15;
    const uint32_t aAddr = sb + A_OFF + (mg * 32 + lrow) * ASTRIDE + (lane >> 4) * 16;

    // per-warp B base (lane-packed fragments)
    const int NTBv = ng * 13;
    const uint2* gwBase = g_wimg + NTBv * 32 + lane;

    float d[26][4];   // [2 m-halves][<=13 n-tiles][4]

    for (int l = 0; l < NHID; ++l) {
        #pragma unroll
        for (int q = 0; q < 26; ++q) {
            d[q][0] = 0.f; d[q][1] = 0.f; d[q][2] = 0.f; d[q][3] = 0.f;
        }
        const uint2* gwl = gwBase + (size_t)l * NKC * 800;

        if (ng == 0) layer_mmas<13>(d, gwl, aAddr);
        else         layer_mmas<12>(d, gwl, aAddr);

        const float* biasL = biasS + l * HIDDEN;
        if (l < NHID - 1) {
            __syncthreads();   // all ldsm reads of this layer's A done
            if (ng == 0) epi_store<0, 13>(d, biasL, mg, g, t, sb);
            else         epi_store<13, 12>(d, biasL, mg, g, t, sb);
            __syncthreads();   // new A visible before next layer's ldsm
        } else {
            if (ng == 0) epi_final<0, 13>(d, biasL, woutS, zp, ng, mg, g, t);
            else         epi_final<13, 12>(d, biasL, woutS, zp, ng, mg, g, t);
        }
    }

    __syncthreads();
    if (tid < TM) {
        int r = row0 + tid;
        if (r < N_NODES) {
            float z = zp[tid] + zp[TM + tid] + __ldg(b_out);
            out[r] = 1.0f / (1.0f + expf(-z));
        }
    }
}

// ---------------- launch ----------------
extern "C" void kernel_launch(void* const* d_in, const int* in_sizes, int n_in,
                              void* d_out, int out_size)
{
    const float* x      = (const float*)d_in[0];
    const int*   ei     = (const int*)d_in[1];      // int32 (jax x64 disabled)
    const float* w_rel  = (const float*)d_in[2];
    const float* b_rel  = (const float*)d_in[3];
    const float* w_root = (const float*)d_in[4];
    const float* w_in   = (const float*)d_in[5];
    const float* b_in   = (const float*)d_in[6];
    const float* w_hid  = (const float*)d_in[7];
    const float* b_hid  = (const float*)d_in[8];
    const float* w_out  = (const float*)d_in[9];
    const float* b_out  = (const float*)d_in[10];
    float*       out    = (float*)d_out;

    cudaFuncSetAttribute(k_mlp, cudaFuncAttributeMaxDynamicSharedMemorySize, SMEM_BYTES);

    k_prep<<<(NHID * NKC * 25 * 32 + 255) / 256, 256>>>(w_hid);
    k_zero<<<(N_NODES + 255) / 256, 256>>>();
    k_scatter<<<(N_EDGES / 4 + 255) / 256, 256>>>(x, ei);
    k_mlp<<<NCTA, THREADS, SMEM_BYTES>>>(
        x, w_rel, b_rel, w_root, w_in, b_in, b_hid, w_out, b_out, out);
}

// round 15
// speedup vs baseline: 1.3487x; 1.3487x over previous
#include <cuda_runtime.h>
#include <cuda_fp16.h>
#include <cstdint>

#define N_NODES 200000
#define N_EDGES 6400000
#define HIDDEN  200
#define NHID    6
#define TM      64
#define THREADS 384
#define NCTA    ((N_NODES + TM - 1) / TM)   // 3125

#define NKC     13                  // k16 chunks (K=200 padded to 208)
#define ASTRIDE 432                 // bytes per activation row (216 fp16, conflict-free)

// smem offsets (bytes) — total 35040, 2 CTAs/SM
#define A_OFF    0                  // 64 x 432 = 27648
#define BIAS_OFF 27648              // 6*200 f32 = 4800
#define WOUT_OFF 32448              // 200 f32 = 800
#define H0_OFF   33248              // 64 f32 = 256
#define ZP_OFF   33504              // 6*64 f32 = 1536
#define SMEM_BYTES 35040

__device__ float g_agg[N_NODES];
// per-lane packed B fragments: idx = ((l*13+kc)*25+nt)*32 + lane -> uint2 {b0,b1}
__device__ __align__(16) uint2 g_wimg[NHID * NKC * 25 * 32];   // 499200 B (L2-resident)

#define PREP_N (NHID * NKC * 25 * 32)   // 312000... actually 6*13*25*32 = 62400*... compute: 6*13=78, 78*25=1950, *32=62400

// ---------------- init kernel: zero agg + build weight image ----------------
__global__ void k_init(const float* __restrict__ w_hid) {
    int idx = blockIdx.x * blockDim.x + threadIdx.x;
    if (idx < N_NODES) g_agg[idx] = 0.0f;
    if (idx < NHID * NKC * 25 * 32) {
        int lane = idx & 31;
        int u = idx >> 5;
        int nt = u % 25; u /= 25;
        int kc = u % NKC; int l = u / NKC;
        int t = lane & 3, g = lane >> 2;
        int n = nt * 8 + g;
        int k0 = kc * 16 + t * 2;
        float w00 = (k0     < HIDDEN) ? w_hid[((size_t)l * HIDDEN + k0    ) * HIDDEN + n] : 0.f;
        float w01 = (k0 + 1 < HIDDEN) ? w_hid[((size_t)l * HIDDEN + k0 + 1) * HIDDEN + n] : 0.f;
        float w10 = (k0 + 8 < HIDDEN) ? w_hid[((size_t)l * HIDDEN + k0 + 8) * HIDDEN + n] : 0.f;
        float w11 = (k0 + 9 < HIDDEN) ? w_hid[((size_t)l * HIDDEN + k0 + 9) * HIDDEN + n] : 0.f;
        __half2 h0 = __floats2half2_rn(w00, w01);
        __half2 h1 = __floats2half2_rn(w10, w11);
        uint2 v;
        v.x = *reinterpret_cast<uint32_t*>(&h0);
        v.y = *reinterpret_cast<uint32_t*>(&h1);
        g_wimg[idx] = v;
    }
}

__global__ void k_scatter(const float* __restrict__ x, const int* __restrict__ ei) {
    int i = blockIdx.x * blockDim.x + threadIdx.x;
    if (i < N_EDGES / 4) {
        const int4 s = reinterpret_cast<const int4*>(ei)[i];
        const int4 d = reinterpret_cast<const int4*>(ei + N_EDGES)[i];
        atomicAdd(&g_agg[d.x], x[s.x]);
        atomicAdd(&g_agg[d.y], x[s.y]);
        atomicAdd(&g_agg[d.z], x[s.z]);
        atomicAdd(&g_agg[d.w], x[s.w]);
    }
}

__device__ __forceinline__ uint32_t packh2(float v0, float v1) {
    __half2 h = __floats2half2_rn(v0, v1);
    return *reinterpret_cast<uint32_t*>(&h);
}

// ---------------- asm helpers ----------------
__device__ __forceinline__ uint32_t s2u(const void* p) {
    uint32_t a;
    asm("{ .reg .u64 t; cvta.to.shared.u64 t, %1; cvt.u32.u64 %0, t; }" : "=r"(a) : "l"(p));
    return a;
}
__device__ __forceinline__ void ldsm4(uint32_t* r, uint32_t a) {
    asm volatile("ldmatrix.sync.aligned.m8n8.x4.shared.b16 {%0,%1,%2,%3}, [%4];"
        : "=r"(r[0]), "=r"(r[1]), "=r"(r[2]), "=r"(r[3]) : "r"(a));
}
__device__ __forceinline__ void sts32(uint32_t a, uint32_t v) {
    asm volatile("st.shared.u32 [%0], %1;" :: "r"(a), "r"(v));
}
__device__ __forceinline__ void mma16816(float* d, const uint32_t* a, uint32_t b0, uint32_t b1) {
    asm volatile("mma.sync.aligned.m16n8k16.row.col.f32.f16.f16.f32 "
        "{%0,%1,%2,%3}, {%4,%5,%6,%7}, {%8,%9}, {%0,%1,%2,%3};"
        : "+f"(d[0]), "+f"(d[1]), "+f"(d[2]), "+f"(d[3])
        : "r"(a[0]), "r"(a[1]), "r"(a[2]), "r"(a[3]), "r"(b0), "r"(b1));
}

// ---------------- layer MMA loop: warp = M32 x NNTW n8-tiles, B from L2/L1 ----------------
// d layout: d[mh*NNTW + nt][4], mh in {0,1} = rows +0..15 / +16..31
template<int NNTW>
__device__ __forceinline__ void layer_mmas(
    float (*d)[4], const uint2* __restrict__ gwl, uint32_t aAddr)
{
    #pragma unroll
    for (int kc = 0; kc < NKC; ++kc) {
        uint32_t a0[4], a1[4];
        ldsm4(a0, aAddr + kc * 32);
        ldsm4(a1, aAddr + 16 * ASTRIDE + kc * 32);

        const uint2* gk = gwl + (size_t)kc * 800;
        uint2 B[NNTW];
        #pragma unroll
        for (int nt = 0; nt < NNTW; ++nt) B[nt] = __ldg(gk + nt * 32);

        #pragma unroll
        for (int nt = 0; nt < NNTW; ++nt) {
            mma16816(d[nt],        a0, B[nt].x, B[nt].y);
            mma16816(d[NNTW + nt], a1, B[nt].x, B[nt].y);
        }
    }
}

template<int NTB, int NNTW>
__device__ __forceinline__ void epi_store(
    const float (*d)[4], const float* biasL, int mg, int g, int t, uint32_t sb)
{
    #pragma unroll
    for (int mh = 0; mh < 2; ++mh) {
        const uint32_t off0 = (uint32_t)(mg * 32 + mh * 16 + g) * ASTRIDE;
        #pragma unroll
        for (int nt = 0; nt < NNTW; ++nt) {
            const float* dd = d[mh * NNTW + nt];
            int c0 = 8 * (NTB + nt) + 2 * t;
            float b0 = biasL[c0], b1 = biasL[c0 + 1];
            float v0 = fmaxf(dd[0] + b0, 0.f), v1 = fmaxf(dd[1] + b1, 0.f);
            float v2 = fmaxf(dd[2] + b0, 0.f), v3 = fmaxf(dd[3] + b1, 0.f);
            uint32_t a0 = off0 + (uint32_t)c0 * 2;
            sts32(sb + A_OFF + a0, packh2(v0, v1));
            sts32(sb + A_OFF + a0 + 8 * ASTRIDE, packh2(v2, v3));
        }
    }
}

template<int NTB, int NNTW>
__device__ __forceinline__ void epi_final(
    const float (*d)[4], const float* biasL, const float* woutS,
    float* zp, int ng, int mg, int g, int t)
{
    #pragma unroll
    for (int mh = 0; mh < 2; ++mh) {
        float z0 = 0.f, z1 = 0.f;
        #pragma unroll
        for (int nt = 0; nt < NNTW; ++nt) {
            const float* dd = d[mh * NNTW + nt];
            int c0 = 8 * (NTB + nt) + 2 * t;
            float b0 = biasL[c0], b1 = biasL[c0 + 1];
            float w0 = woutS[c0], w1 = woutS[c0 + 1];
            z0 = fmaf(fmaxf(dd[0] + b0, 0.f), w0, z0);
            z0 = fmaf(fmaxf(dd[1] + b1, 0.f), w1, z0);
            z1 = fmaf(fmaxf(dd[2] + b0, 0.f), w0, z1);
            z1 = fmaf(fmaxf(dd[3] + b1, 0.f), w1, z1);
        }
        z0 += __shfl_xor_sync(0xffffffffu, z0, 1);
        z0 += __shfl_xor_sync(0xffffffffu, z0, 2);
        z1 += __shfl_xor_sync(0xffffffffu, z1, 1);
        z1 += __shfl_xor_sync(0xffffffffu, z1, 2);
        if (t == 0) {
            int rl = mg * 32 + mh * 16 + g;
            zp[ng * TM + rl]     = z0;
            zp[ng * TM + rl + 8] = z1;
        }
    }
}

// ---------------- fused GraphConv + MLP + sigmoid ----------------
__global__ void __launch_bounds__(THREADS, 2) k_mlp(
    const float* __restrict__ x,
    const float* __restrict__ w_rel, const float* __restrict__ b_rel,
    const float* __restrict__ w_root,
    const float* __restrict__ w_in,  const float* __restrict__ b_in,
    const float* __restrict__ b_hid,
    const float* __restrict__ w_out, const float* __restrict__ b_out,
    float* __restrict__ out)
{
    extern __shared__ char smem[];
    const uint32_t sb = s2u(smem);
    const int tid  = threadIdx.x;
    const int warp = tid >> 5;         // 0..11
    const int lane = tid & 31;
    const int ng   = warp >> 1;        // n-group 0..5: tiles {0:0-4, 1:5-8, 2:9-12, 3:13-16, 4:17-20, 5:21-24}
    const int mg   = warp & 1;         // m-group: rows mg*32 .. +31
    const int g    = lane >> 2;
    const int t    = lane & 3;
    const int row0 = blockIdx.x * TM;

    float* biasS = reinterpret_cast<float*>(smem + BIAS_OFF);   // [6][200]
    float* woutS = reinterpret_cast<float*>(smem + WOUT_OFF);
    float* h0S   = reinterpret_cast<float*>(smem + H0_OFF);
    float* zp    = reinterpret_cast<float*>(smem + ZP_OFF);     // [6][64]

    // stage small vectors + h0
    if (tid < HIDDEN) woutS[tid] = __ldg(w_out + tid);
    for (int i = tid; i < NHID * HIDDEN; i += THREADS) biasS[i] = __ldg(b_hid + i);
    if (tid < TM) {
        int r = row0 + tid;
        float a  = (r < N_NODES) ? g_agg[r] : 0.0f;
        float xv = (r < N_NODES) ? __ldg(x + r) : 0.0f;
        h0S[tid] = a * __ldg(w_rel) + __ldg(b_rel) + xv * __ldg(w_root);
    }
    __syncthreads();

    // layer-1 activations (rank-1): A[r][k] = relu(h0[r]*w_in[k]+b_in[k]), k>=200 -> 0
    for (int i = tid; i < TM * 208; i += THREADS) {
        int r = i / 208, k = i - r * 208;
        float v = 0.0f;
        if (k < HIDDEN) v = fmaxf(fmaf(h0S[r], __ldg(w_in + k), __ldg(b_in + k)), 0.0f);
        *reinterpret_cast<__half*>(smem + A_OFF + r * ASTRIDE + k * 2) = __float2half_rn(v);
    }
    __syncthreads();

    // ldmatrix per-lane address (rows mg*32 .. +15; second half at +16*ASTRIDE)
    const int lrow = lane & 15;
    const uint32_t aAddr = sb + A_OFF + (mg * 32 + lrow) * ASTRIDE + (lane >> 4) * 16;

    // per-warp B base (lane-packed fragments); tile bases: 0,5,9,13,17,21
    const int NTBv = (ng == 0) ? 0 : (4 * ng + 1);
    const uint2* gwBase = g_wimg + NTBv * 32 + lane;

    float d[10][4];   // [2 m-halves][<=5 n-tiles][4]

    for (int l = 0; l < NHID; ++l) {
        #pragma unroll
        for (int q = 0; q < 10; ++q) {
            d[q][0] = 0.f; d[q][1] = 0.f; d[q][2] = 0.f; d[q][3] = 0.f;
        }
        const uint2* gwl = gwBase + (size_t)l * NKC * 800;

        if (ng == 0) layer_mmas<5>(d, gwl, aAddr);
        else         layer_mmas<4>(d, gwl, aAddr);

        const float* biasL = biasS + l * HIDDEN;
        if (l < NHID - 1) {
            __syncthreads();   // all ldsm reads of this layer's A done
            switch (ng) {
                case 0: epi_store<0, 5>(d, biasL, mg, g, t, sb); break;
                case 1: epi_store<5, 4>(d, biasL, mg, g, t, sb); break;
                case 2: epi_store<9, 4>(d, biasL, mg, g, t, sb); break;
                case 3: epi_store<13, 4>(d, biasL, mg, g, t, sb); break;
                case 4: epi_store<17, 4>(d, biasL, mg, g, t, sb); break;
                default: epi_store<21, 4>(d, biasL, mg, g, t, sb); break;
            }
            __syncthreads();   // new A visible before next layer's ldsm
        } else {
            switch (ng) {
                case 0: epi_final<0, 5>(d, biasL, woutS, zp, ng, mg, g, t); break;
                case 1: epi_final<5, 4>(d, biasL, woutS, zp, ng, mg, g, t); break;
                case 2: epi_final<9, 4>(d, biasL, woutS, zp, ng, mg, g, t); break;
                case 3: epi_final<13, 4>(d, biasL, woutS, zp, ng, mg, g, t); break;
                case 4: epi_final<17, 4>(d, biasL, woutS, zp, ng, mg, g, t); break;
                default: epi_final<21, 4>(d, biasL, woutS, zp, ng, mg, g, t); break;
            }
        }
    }

    __syncthreads();
    if (tid < TM) {
        int r = row0 + tid;
        if (r < N_NODES) {
            float z = zp[tid] + zp[TM + tid] + zp[2 * TM + tid]
                    + zp[3 * TM + tid] + zp[4 * TM + tid] + zp[5 * TM + tid] + __ldg(b_out);
            out[r] = 1.0f / (1.0f + expf(-z));
        }
    }
}

// ---------------- launch ----------------
extern "C" void kernel_launch(void* const* d_in, const int* in_sizes, int n_in,
                              void* d_out, int out_size)
{
    const float* x      = (const float*)d_in[0];
    const int*   ei     = (const int*)d_in[1];      // int32 (jax x64 disabled)
    const float* w_rel  = (const float*)d_in[2];
    const float* b_rel  = (const float*)d_in[3];
    const float* w_root = (const float*)d_in[4];
    const float* w_in   = (const float*)d_in[5];
    const float* b_in   = (const float*)d_in[6];
    const float* w_hid  = (const float*)d_in[7];
    const float* b_hid  = (const float*)d_in[8];
    const float* w_out  = (const float*)d_in[9];
    const float* b_out  = (const float*)d_in[10];
    float*       out    = (float*)d_out;

    cudaFuncSetAttribute(k_mlp, cudaFuncAttributeMaxDynamicSharedMemorySize, SMEM_BYTES);

    // one launch covers both agg-zero (200000) and weight-image build (62400)
    k_init<<<(N_NODES + 255) / 256, 256>>>(w_hid);
    k_scatter<<<(N_EDGES / 4 + 255) / 256, 256>>>(x, ei);
    k_mlp<<<NCTA, THREADS, SMEM_BYTES>>>(
        x, w_rel, b_rel, w_root, w_in, b_in, b_hid, w_out, b_out, out);
}